// round 16
// baseline (speedup 1.0000x reference)
#include <cuda_runtime.h>
#include <cuda_fp16.h>
#include <math.h>
#include <stdint.h>

// ---------------------------------------------------------------------------
#define Bn 8
#define H 64
#define W 128
#define HW (H * W)
#define C1CH 96
#define HIN 32
#define WIN 64
#define HWIN (HIN * WIN)
#define PREVC 661

#define FEAT_C 629
#define FEAT_STRIDE (FEAT_C * HW)

// [c5(32) | c4(64) | c3(96) | c2(128) | c1(128) | vol(81) | tenOne(96) | flow(2) | upfeat(2)]
#define OFF_C5   0
#define OFF_C4   32
#define OFF_C3   96
#define OFF_C2   192
#define OFF_C1   320
#define OFF_VOL  448
#define OFF_T1   529
#define OFF_FLOW 625
#define OFF_UPF  627

#define NQG 40                         // 640-channel padded space / 16

__device__ float g_warped[(size_t)Bn * C1CH * HW];

// quad-interleaved fp16 shadow: per (b, g16, pix): 4 u64 slots,
// slot s = {half2(ch 16g+2s, +1), half2(ch 16g+8+2s, +1)}.
__device__ unsigned long long g_halfq[(size_t)Bn * NQG * HW * 4];

// fp16 A-fragments, chunk = 144 k; k-order: tap-major (ks=tap), channel-minor
#define APACK_OFF1 0
#define APACK_OFF2 110592      // + 12*9*8*128
#define APACK_OFF3 294912      // + 20*9*8*128
#define APACK_OFF4 488448      // + 28*9*6*128
#define APACK_OFF5 645120      // + 34*9*4*128
#define APACK_TOTAL 732672     // + 38*9*2*128
__device__ uint32_t g_Apack[APACK_TOTAL];

// per-parity packed upconv weights: [parity 4][ci 663][8 floats]
__device__ float g_upw[4 * 663 * 8];

// ---------------------------------------------------------------------------
__device__ __forceinline__ uint32_t smem_u32(const void* p) {
    uint32_t a;
    asm("{ .reg .u64 t; cvta.to.shared.u64 t, %1; cvt.u32.u64 %0, t; }" : "=r"(a) : "l"(p));
    return a;
}
__device__ __forceinline__ void cp_async16(uint32_t dst, const void* src) {
    asm volatile("cp.async.ca.shared.global [%0], [%1], 16;" :: "r"(dst), "l"(src));
}
#define CP_COMMIT() asm volatile("cp.async.commit_group;")
#define CP_WAIT0()  asm volatile("cp.async.wait_group 0;")
#define CP_WAIT1()  asm volatile("cp.async.wait_group 1;")

// scalar write into the quad-interleaved shadow
__device__ __forceinline__ void st_half(int b, int ch, int pix, float v) {
    int g16 = ch >> 4, r = ch & 15;
    int pos = 4 * ((r & 7) >> 1) + ((r >> 3) << 1) + (r & 1);
    __half* hp = (__half*)g_halfq + (((size_t)b * NQG + g16) * HW + pix) * 16 + pos;
    *hp = __float2half_rn(v);
}

__device__ __forceinline__ uint32_t pk2h(float a, float b) {
    __half ha = __float2half_rn(a), hb = __float2half_rn(b);
    return (uint32_t)__half_as_ushort(ha) | ((uint32_t)__half_as_ushort(hb) << 16);
}

#define MMA_F16(c, a0, a1, a2, a3, b0v, b1v) \
    asm volatile( \
        "mma.sync.aligned.m16n8k16.row.col.f32.f16.f16.f32 " \
        "{%0,%1,%2,%3}, {%4,%5,%6,%7}, {%8,%9}, {%0,%1,%2,%3};" \
        : "+f"((c)[0]), "+f"((c)[1]), "+f"((c)[2]), "+f"((c)[3]) \
        : "r"(a0), "r"(a1), "r"(a2), "r"(a3), \
          "r"(b0v), "r"(b1v))

// ---------------------------------------------------------------------------
// Weight pre-pack (unchanged layout)
// ---------------------------------------------------------------------------
__device__ __forceinline__ void pack_one(const float* w, uint32_t* dst, int idx,
                                         int Cin, int Cout)
{
    int MFT = Cout >> 4;
    int reg = idx & 3, lane = (idx >> 2) & 31;
    int u = idx >> 7;
    int mf = u % MFT;
    int v3 = u / MFT;
    int ks = v3 % 9, kt = v3 / 9;
    int m = mf * 16 + (lane >> 2) + 8 * (reg & 1);
    int ch = kt * 16 + (lane & 3) * 2 + 8 * (reg >> 1);
    float v0 = (ch     < Cin) ? w[((size_t)m * Cin + ch)     * 9 + ks] : 0.f;
    float v1 = (ch + 1 < Cin) ? w[((size_t)m * Cin + ch + 1) * 9 + ks] : 0.f;
    __half h0 = __float2half_rn(v0), h1 = __float2half_rn(v1);
    dst[idx] = (uint32_t)__half_as_ushort(h0) | ((uint32_t)__half_as_ushort(h1) << 16);
}

__global__ void pack_all_kernel(const float* __restrict__ w1, const float* __restrict__ w2,
                                const float* __restrict__ w3, const float* __restrict__ w4,
                                const float* __restrict__ w5, uint32_t* __restrict__ dst)
{
    int idx = blockIdx.x * blockDim.x + threadIdx.x;
    if (idx >= APACK_TOTAL) return;
    if      (idx < APACK_OFF2) pack_one(w1, dst + APACK_OFF1, idx - APACK_OFF1, 181, 128);
    else if (idx < APACK_OFF3) pack_one(w2, dst + APACK_OFF2, idx - APACK_OFF2, 309, 128);
    else if (idx < APACK_OFF4) pack_one(w3, dst + APACK_OFF3, idx - APACK_OFF3, 437, 96);
    else if (idx < APACK_OFF5) pack_one(w4, dst + APACK_OFF4, idx - APACK_OFF4, 533, 64);
    else                       pack_one(w5, dst + APACK_OFF5, idx - APACK_OFF5, 597, 32);
}

// per-parity upconv weight pack: [parity][ci_all(663)][8]
__global__ void pack_upw_kernel(const float* __restrict__ wF, const float* __restrict__ wU,
                                float* __restrict__ dst)
{
    int idx = blockIdx.x * blockDim.x + threadIdx.x;
    if (idx >= 4 * 663 * 8) return;
    int j = idx & 7;
    int q = idx >> 3;
    int ci_all = q % 663, parity = q / 663;
    int py = parity >> 1, px = parity & 1;
    int ky0 = 1 + py, ky1 = py ? 0 : 3;
    int kx0 = 1 + px, kx1 = px ? 0 : 3;
    int cout = j >> 2, tp = j & 3;
    int ky = (tp < 2) ? ky0 : ky1;
    int kx = (tp & 1) ? kx1 : kx0;
    const float* src;
    int ci;
    if (ci_all < 2) { src = wF; ci = ci_all; }
    else            { src = wU; ci = ci_all - 2; }
    dst[idx] = src[(size_t)ci * 32 + cout * 16 + ky * 4 + kx];
}

// ---------------------------------------------------------------------------
// Flow upconv: per-pixel, Cin = 2 (trivial)
// ---------------------------------------------------------------------------
__global__ void upflow_kernel(const float* __restrict__ inF, const float* __restrict__ bF,
                              float* __restrict__ feat)
{
    int gid = blockIdx.x * blockDim.x + threadIdx.x;
    if (gid >= Bn * HW) return;
    int b = gid / HW, pix = gid - b * HW;
    int y = pix / W, x = pix - (pix / W) * W;
    int iy0 = y >> 1, iy1 = (y >> 1) + ((y & 1) ? 1 : -1);
    int ix0 = x >> 1, ix1 = (x >> 1) + ((x & 1) ? 1 : -1);
    bool vy1 = (unsigned)iy1 < HIN, vx1 = (unsigned)ix1 < WIN;
    int parity = (y & 1) * 2 + (x & 1);
    const float* wb = g_upw + (size_t)parity * (663 * 8);
    float a0 = bF[0], a1 = bF[1];
    const float* pin = inF + (size_t)b * 2 * HWIN;
    int p00 = iy0 * WIN + ix0, p01 = iy0 * WIN + ix1;
    int p10 = iy1 * WIN + ix0, p11 = iy1 * WIN + ix1;
#pragma unroll
    for (int ci = 0; ci < 2; ci++) {
        const float* p = pin + (size_t)ci * HWIN;
        float4 f0 = *(const float4*)(wb + ci * 8);
        float4 f1 = *(const float4*)(wb + ci * 8 + 4);
        float u0 = p[p00];
        float u1 = vx1 ? p[p01] : 0.f;
        float u2 = vy1 ? p[p10] : 0.f;
        float u3 = (vy1 && vx1) ? p[p11] : 0.f;
        a0 += u0 * f0.x + u1 * f0.y + u2 * f0.z + u3 * f0.w;
        a1 += u0 * f1.x + u1 * f1.y + u2 * f1.z + u3 * f1.w;
    }
    size_t o = (size_t)b * FEAT_STRIDE + (size_t)OFF_FLOW * HW + pix;
    feat[o]      = a0;
    feat[o + HW] = a1;
    st_half(b, OFF_FLOW,     pix, a0);
    st_half(b, OFF_FLOW + 1, pix, a1);
}

// ---------------------------------------------------------------------------
// Tiled upfeat upconv: CTA = 64x4 output tile; per channel stage a 4x34 input
// patch + 32 parity weights into smem (double-buffered, 1 sync/channel).
// LDG per channel drops 1024 -> 168 per CTA.
// ---------------------------------------------------------------------------
__global__ __launch_bounds__(256) void upfeat_tiled_kernel(const float* __restrict__ in,
                                                           const float* __restrict__ bias,
                                                           float* __restrict__ feat)
{
    __shared__ float s_in[2][4 * 34];
    __shared__ float s_w[2][32];
    const int tid = threadIdx.x;
    const int x0 = (blockIdx.x & 1) << 6;
    const int y0 = (blockIdx.x >> 1) << 2;
    const int b = blockIdx.y;
    const int x = x0 + (tid & 63), y = y0 + (tid >> 6);
    const int Y = y0 >> 1, X = x0 >> 1;
    const float* pin = in + (size_t)b * PREVC * HWIN;

    const int ry0 = 1 + ((y - y0) >> 1);
    const int ry1 = (y & 1) ? ry0 + 1 : ry0 - 1;
    const int rx0 = 1 + ((x - x0) >> 1);
    const int rx1 = (x & 1) ? rx0 + 1 : rx0 - 1;
    const int parity = (y & 1) * 2 + (x & 1);

    // stage channel ci into buffer s
    auto stageCh = [&](int ci, int s) {
        if (tid < 136) {
            int r = tid / 34, c = tid - (tid / 34) * 34;
            int iy = Y - 1 + r, ix = X - 1 + c;
            float v = 0.f;
            if ((unsigned)iy < HIN && (unsigned)ix < WIN)
                v = pin[(size_t)ci * HWIN + iy * WIN + ix];
            s_in[s][r * 34 + c] = v;
        } else if (tid < 168) {
            int j = tid - 136;
            s_w[s][j] = g_upw[(size_t)(j >> 3) * (663 * 8) + (size_t)(ci + 2) * 8 + (j & 7)];
        }
    };

    float a0 = bias[0], a1 = bias[1];
    stageCh(0, 0);
    for (int ci = 0; ci < PREVC; ci++) {
        __syncthreads();
        if (ci + 1 < PREVC) stageCh(ci + 1, (ci + 1) & 1);
        const float* si = s_in[ci & 1];
        const float* sw = s_w[ci & 1] + parity * 8;
        float u0 = si[ry0 * 34 + rx0];
        float u1 = si[ry0 * 34 + rx1];
        float u2 = si[ry1 * 34 + rx0];
        float u3 = si[ry1 * 34 + rx1];
        float4 f0 = *(const float4*)(sw);
        float4 f1 = *(const float4*)(sw + 4);
        a0 += u0 * f0.x + u1 * f0.y + u2 * f0.z + u3 * f0.w;
        a1 += u0 * f1.x + u1 * f1.y + u2 * f1.z + u3 * f1.w;
    }
    int pix = y * W + x;
    size_t o = (size_t)b * FEAT_STRIDE + (size_t)OFF_UPF * HW + pix;
    feat[o]      = a0;
    feat[o + HW] = a1;
    st_half(b, OFF_UPF,     pix, a0);
    st_half(b, OFF_UPF + 1, pix, a1);
}

// ---------------------------------------------------------------------------
// tenOne -> feat + shadow; full 16-ch groups written as 2x ST.128 per pixel
// ---------------------------------------------------------------------------
__global__ void copy_t1_kernel(const float* __restrict__ t1, float* __restrict__ feat)
{
    int gid = blockIdx.x * blockDim.x + threadIdx.x;
    if (gid >= Bn * HW) return;
    int b = gid / HW, pix = gid - b * HW;
    const float* src = t1 + (size_t)b * C1CH * HW + pix;
    float* dstF = feat + (size_t)b * FEAT_STRIDE + (size_t)OFF_T1 * HW + pix;
    __half* hbase = (__half*)g_halfq + ((size_t)b * NQG) * HW * 16;

    // partial group 33: ch 529..543 = j 0..14 (scalar)
#pragma unroll
    for (int j = 0; j < 15; j++) {
        float v = src[(size_t)j * HW];
        dstF[(size_t)j * HW] = v;
        st_half(b, 529 + j, pix, v);
    }
    // full groups 34..38: ch 544..623 = j 15..94
#pragma unroll
    for (int gi = 0; gi < 5; gi++) {
        int j0 = 15 + gi * 16;
        float w[16];
#pragma unroll
        for (int s = 0; s < 16; s++) {
            w[s] = src[(size_t)(j0 + s) * HW];
            dstF[(size_t)(j0 + s) * HW] = w[s];
        }
        uint4* dst = (uint4*)(hbase + ((size_t)(34 + gi) * HW + pix) * 16);
        dst[0] = make_uint4(pk2h(w[0], w[1]), pk2h(w[8],  w[9]),
                            pk2h(w[2], w[3]), pk2h(w[10], w[11]));
        dst[1] = make_uint4(pk2h(w[4], w[5]), pk2h(w[12], w[13]),
                            pk2h(w[6], w[7]), pk2h(w[14], w[15]));
    }
    // ch 624 = j 95 (group 39, r = 0)
    {
        float v = src[(size_t)95 * HW];
        dstF[(size_t)95 * HW] = v;
        st_half(b, 624, pix, v);
    }
}

__global__ void warp_kernel(const float* __restrict__ tenTwo, const float* __restrict__ feat)
{
    int gid = blockIdx.x * blockDim.x + threadIdx.x;
    if (gid >= Bn * HW) return;
    int b = gid / HW;
    int pix = gid - b * HW;
    int y = pix / W, x = pix - (pix / W) * W;

    const float* fl = feat + (size_t)b * FEAT_STRIDE + (size_t)OFF_FLOW * HW + pix;
    float px = (float)x + fl[0]  * 1.25f;
    float py = (float)y + fl[HW] * 1.25f;
    float fx = floorf(px), fy = floorf(py);
    float wx = px - fx, wy = py - fy;
    int ix0 = (int)fx, iy0 = (int)fy;
    int ix1 = ix0 + 1, iy1 = iy0 + 1;
    bool vx0 = (unsigned)ix0 < W, vx1 = (unsigned)ix1 < W;
    bool vy0 = (unsigned)iy0 < H, vy1 = (unsigned)iy1 < H;
    float w00 = (1.f - wy) * (1.f - wx), w01 = (1.f - wy) * wx;
    float w10 = wy * (1.f - wx),         w11 = wy * wx;
    int o00 = iy0 * W + ix0, o01 = iy0 * W + ix1;
    int o10 = iy1 * W + ix0, o11 = iy1 * W + ix1;

    const float* t = tenTwo + (size_t)b * C1CH * HW;
    float* o = g_warped + (size_t)b * C1CH * HW + pix;
    for (int c = 0; c < C1CH; c++) {
        const float* tc = t + (size_t)c * HW;
        float v = 0.f;
        if (vy0 && vx0) v += tc[o00] * w00;
        if (vy0 && vx1) v += tc[o01] * w01;
        if (vy1 && vx0) v += tc[o10] * w10;
        if (vy1 && vx1) v += tc[o11] * w11;
        o[(size_t)c * HW] = v;
    }
}

__global__ __launch_bounds__(128) void corr_kernel(const float* __restrict__ tenOne,
                                                   float* __restrict__ feat)
{
    __shared__ float s_f1[4][32];
    __shared__ float s_w2[12][40];
    int tid = threadIdx.x;
    int tx = tid & 31, ty = tid >> 5;
    int x0 = blockIdx.x * 32, y0 = blockIdx.y * 4, b = blockIdx.z;

    float acc[81];
#pragma unroll
    for (int d = 0; d < 81; d++) acc[d] = 0.f;

    const float* f1 = tenOne + (size_t)b * C1CH * HW;
    const float* f2 = g_warped + (size_t)b * C1CH * HW;

    for (int c = 0; c < C1CH; c++) {
        const float* f1c = f1 + (size_t)c * HW;
        const float* f2c = f2 + (size_t)c * HW;
        __syncthreads();
        s_f1[ty][tx] = f1c[(y0 + ty) * W + x0 + tx];
#pragma unroll
        for (int i = 0; i < 4; i++) {
            int idx = tid + i * 128;
            if (idx < 480) {
                int r = idx / 40, cc = idx - (idx / 40) * 40;
                int gy = y0 - 4 + r, gx = x0 - 4 + cc;
                float v = 0.f;
                if ((unsigned)gy < H && (unsigned)gx < W) v = f2c[gy * W + gx];
                s_w2[r][cc] = v;
            }
        }
        __syncthreads();
        float a = s_f1[ty][tx];
#pragma unroll
        for (int dy = 0; dy < 9; dy++)
#pragma unroll
            for (int dx = 0; dx < 9; dx++)
                acc[dy * 9 + dx] += a * s_w2[ty + dy][tx + dx];
    }

    int pix = (y0 + ty) * W + x0 + tx;
    size_t obase = (size_t)b * FEAT_STRIDE + (size_t)OFF_VOL * HW + pix;
    const float inv = 1.f / 96.f;
    float r[81];
#pragma unroll
    for (int d = 0; d < 81; d++) {
        float v = acc[d] * inv;
        v = (v >= 0.f) ? v : 0.1f * v;
        r[d] = v;
        feat[obase + (size_t)d * HW] = v;
    }
    // shadow: groups 28..32 full (d 0..79) vectorized; d = 80 (ch 528) scalar
    __half* hbase = (__half*)g_halfq + ((size_t)b * NQG) * HW * 16;
#pragma unroll
    for (int gi = 0; gi < 5; gi++) {
        int d0 = gi * 16;
        uint4* dst = (uint4*)(hbase + ((size_t)(28 + gi) * HW + pix) * 16);
        dst[0] = make_uint4(pk2h(r[d0 + 0], r[d0 + 1]), pk2h(r[d0 + 8],  r[d0 + 9]),
                            pk2h(r[d0 + 2], r[d0 + 3]), pk2h(r[d0 + 10], r[d0 + 11]));
        dst[1] = make_uint4(pk2h(r[d0 + 4], r[d0 + 5]), pk2h(r[d0 + 12], r[d0 + 13]),
                            pk2h(r[d0 + 6], r[d0 + 7]), pk2h(r[d0 + 14], r[d0 + 15]));
    }
    st_half(b, 528, pix, r[80]);
}

// ---------------------------------------------------------------------------
// FFMA direct 3x3 conv (conv6, Cout=2)
// ---------------------------------------------------------------------------
template <int COUT_BLK>
__global__ __launch_bounds__(256) void conv3x3_kernel(
    const float* __restrict__ in, const float* __restrict__ w,
    const float* __restrict__ bias, float* __restrict__ out,
    int Cin, int inStride, int outStride)
{
    __shared__ float s_in[18][66];
    __shared__ float s_w[COUT_BLK * 9];
    const int tid = threadIdx.x;
    const int tx = tid & 15, ty = tid >> 4;
    const int g = blockIdx.x;
    const int tileX = blockIdx.y & 1, tileY = blockIdx.y >> 1;
    const int b = blockIdx.z;
    const int x0 = tileX * 64, y0 = tileY * 16;

    const float* inB = in + (size_t)b * inStride;
    float acc[COUT_BLK][4];
#pragma unroll
    for (int c = 0; c < COUT_BLK; c++)
#pragma unroll
        for (int p = 0; p < 4; p++) acc[c][p] = 0.f;

    for (int ci = 0; ci < Cin; ci++) {
        const float* ch = inB + (size_t)ci * HW;
#pragma unroll
        for (int i = 0; i < 5; i++) {
            int idx = tid + i * 256;
            if (idx < 18 * 66) {
                int r = idx / 66, c = idx - (idx / 66) * 66;
                int gy = y0 - 1 + r, gx = x0 - 1 + c;
                float v = 0.f;
                if ((unsigned)gy < H && (unsigned)gx < W) v = ch[gy * W + gx];
                s_in[r][c] = v;
            }
        }
        if (tid < COUT_BLK * 9)
            s_w[tid] = w[((size_t)(g * COUT_BLK + tid / 9) * Cin + ci) * 9 + tid % 9];
        __syncthreads();

        float r0[6], r1[6], r2[6];
#pragma unroll
        for (int k = 0; k < 6; k++) {
            r0[k] = s_in[ty][tx * 4 + k];
            r1[k] = s_in[ty + 1][tx * 4 + k];
            r2[k] = s_in[ty + 2][tx * 4 + k];
        }
#pragma unroll
        for (int co = 0; co < COUT_BLK; co++) {
            float w0 = s_w[co * 9 + 0], w1v = s_w[co * 9 + 1], w2v = s_w[co * 9 + 2];
            float w3v = s_w[co * 9 + 3], w4v = s_w[co * 9 + 4], w5v = s_w[co * 9 + 5];
            float w6v = s_w[co * 9 + 6], w7v = s_w[co * 9 + 7], w8v = s_w[co * 9 + 8];
#pragma unroll
            for (int p = 0; p < 4; p++) {
                float s = acc[co][p];
                s += w0  * r0[p]; s += w1v * r0[p + 1]; s += w2v * r0[p + 2];
                s += w3v * r1[p]; s += w4v * r1[p + 1]; s += w5v * r1[p + 2];
                s += w6v * r2[p]; s += w7v * r2[p + 1]; s += w8v * r2[p + 2];
                acc[co][p] = s;
            }
        }
        __syncthreads();
    }

#pragma unroll
    for (int co = 0; co < COUT_BLK; co++) {
        float bi = bias[g * COUT_BLK + co];
        float* o = out + (size_t)b * outStride + (size_t)(g * COUT_BLK + co) * HW
                 + (y0 + ty) * W + x0 + tx * 4;
#pragma unroll
        for (int p = 0; p < 4; p++) {
            float v = acc[co][p] + bi;
            o[p] = (v >= 0.f) ? v : 0.1f * v;
        }
    }
}

// ---------------------------------------------------------------------------
// conv_mma6: N=64 tiles, quad-interleaved B -> one LDS.64 per b-fragment.
// ---------------------------------------------------------------------------
#define SRQ 268                 // u64 per staged row
#define BUFQ (3 * SRQ)          // u64 per buffer

template <int Cin, int Cout, int THREADS, int MINB>
__global__ __launch_bounds__(THREADS, MINB) void conv_mma6_kernel(
    int base16,
    const uint4* __restrict__ Apack,
    const float* __restrict__ bias,
    float* __restrict__ outBase,
    int outOff)
{
    constexpr int nC  = (Cin + 15) / 16;
    constexpr int MFT = Cout / 16;

    __shared__ unsigned long long rawq[2 * BUFQ];
    const int tid = threadIdx.x, lane = tid & 31, wrp = tid >> 5;
    const int wm0 = wrp * 32;
    const int y  = blockIdx.x >> 1;
    const int x0 = (blockIdx.x & 1) << 6;
    const int b  = blockIdx.y;
    const unsigned long long* inQ = g_halfq + (size_t)b * NQG * HW * 4;
    const uint32_t rawAddr = smem_u32(rawq);
    const uint4* apw = Apack + (size_t)(wrp * 2) * 32 + lane;

    float acc[2][8][4];
#pragma unroll
    for (int mi = 0; mi < 2; mi++)
#pragma unroll
        for (int nf = 0; nf < 8; nf++)
#pragma unroll
            for (int p = 0; p < 4; p++) acc[mi][nf][p] = 0.f;

    auto stage = [&](int kt, int bufsel) {
        const unsigned long long* src = inQ + (size_t)(base16 + kt) * HW * 4;
        for (int i = tid; i < 384; i += THREADS) {
            int r = i >> 7, j = i & 127;
            int p = j >> 1, hs = j & 1;
            int yr = y + r - 1;
            uint32_t didx = (uint32_t)(bufsel * BUFQ + r * SRQ + (1 + p) * 4 + hs * 2);
            if ((unsigned)yr < (unsigned)H)
                cp_async16(rawAddr + didx * 8, src + ((size_t)yr * W + x0 + p) * 4 + hs * 2);
            else
                *(uint4*)(rawq + didx) = make_uint4(0u, 0u, 0u, 0u);
        }
        for (int e = tid; e < 12; e += THREADS) {
            int r = e >> 2, j = e & 3;
            int side = j >> 1, hs = j & 1;
            int yr = y + r - 1;
            int x = side ? (x0 + 64) : (x0 - 1);
            uint32_t didx = (uint32_t)(bufsel * BUFQ + r * SRQ + (side ? 260 : 0) + hs * 2);
            if ((unsigned)yr < (unsigned)H && (unsigned)x < (unsigned)W)
                cp_async16(rawAddr + didx * 8, src + ((size_t)yr * W + x) * 4 + hs * 2);
            else
                *(uint4*)(rawq + didx) = make_uint4(0u, 0u, 0u, 0u);
        }
    };

    stage(0, 0);
    CP_COMMIT();

    const int t = lane & 3;
    const int g = lane >> 2;

    uint4 ah0, ah1;
    { const uint4* p = apw; ah0 = p[0]; ah1 = p[32]; }

    for (int kt = 0; kt < nC; kt++) {
        const int buf = kt & 1;
        if (kt + 1 < nC) {
            stage(kt + 1, buf ^ 1);
            CP_COMMIT();
            CP_WAIT1();
        } else {
            CP_WAIT0();
        }
        __syncthreads();

        const unsigned long long* rbq = rawq + buf * BUFQ;

#pragma unroll
        for (int ks = 0; ks < 9; ks++) {
            uint4 nh0, nh1;
            {
                int nkt = kt, nks = ks + 1;
                if (nks == 9) { nkt = kt + 1; nks = 0; }
                if (nkt < nC) {
                    const uint4* p = apw + (size_t)((nkt * 9 + nks) * MFT) * 32;
                    nh0 = p[0]; nh1 = p[32];
                } else {
                    nh0 = nh1 = make_uint4(0u, 0u, 0u, 0u);
                }
            }

            const int dy = ks / 3, dx = ks % 3;
            const unsigned long long* bp = rbq + dy * SRQ + (g + dx) * 4 + t;

#pragma unroll
            for (int nf = 0; nf < 8; nf += 2) {
                unsigned long long vA = bp[nf * 32];
                unsigned long long vB = bp[nf * 32 + 32];
                uint32_t bA0 = (uint32_t)vA, bA1 = (uint32_t)(vA >> 32);
                uint32_t bB0 = (uint32_t)vB, bB1 = (uint32_t)(vB >> 32);
                MMA_F16(acc[0][nf],     ah0.x, ah0.y, ah0.z, ah0.w, bA0, bA1);
                MMA_F16(acc[1][nf],     ah1.x, ah1.y, ah1.z, ah1.w, bA0, bA1);
                MMA_F16(acc[0][nf + 1], ah0.x, ah0.y, ah0.z, ah0.w, bB0, bB1);
                MMA_F16(acc[1][nf + 1], ah1.x, ah1.y, ah1.z, ah1.w, bB0, bB1);
            }
            ah0 = nh0; ah1 = nh1;
        }
        __syncthreads();
    }

    const int q = lane & 3, g2 = lane >> 2;
    float* outB = outBase + (size_t)b * FEAT_STRIDE;
    __half* hq = (__half*)g_halfq + ((size_t)b * NQG) * HW * 16;
#pragma unroll
    for (int mi = 0; mi < 2; mi++) {
        int m0 = wm0 + mi * 16 + g2;
        int am = outOff + m0;
        float bLo = __ldg(bias + m0), bHi = __ldg(bias + m0 + 8);
        float* o0 = outB + (size_t)m0 * HW;
        float* o1 = o0 + 8 * HW;
        size_t hb = (size_t)(am >> 4) * HW * 16 + 4 * ((am & 15) >> 1) + (am & 1);
#pragma unroll
        for (int nf = 0; nf < 8; nf++) {
            int off = y * W + x0 + nf * 8 + 2 * q;
            float v0 = acc[mi][nf][0] + bLo, v1 = acc[mi][nf][1] + bLo;
            float v2 = acc[mi][nf][2] + bHi, v3 = acc[mi][nf][3] + bHi;
            v0 = (v0 >= 0.f) ? v0 : 0.1f * v0;
            v1 = (v1 >= 0.f) ? v1 : 0.1f * v1;
            v2 = (v2 >= 0.f) ? v2 : 0.1f * v2;
            v3 = (v3 >= 0.f) ? v3 : 0.1f * v3;
            *(float2*)(o0 + off) = make_float2(v0, v1);
            *(float2*)(o1 + off) = make_float2(v2, v3);
            size_t h = hb + (size_t)off * 16;
            hq[h]      = __float2half_rn(v0);
            hq[h + 2]  = __float2half_rn(v2);
            hq[h + 16] = __float2half_rn(v1);
            hq[h + 18] = __float2half_rn(v3);
        }
    }
}

// ---------------------------------------------------------------------------
// Launch
// ---------------------------------------------------------------------------
extern "C" void kernel_launch(void* const* d_in, const int* in_sizes, int n_in,
                              void* d_out, int out_size)
{
    (void)in_sizes; (void)n_in; (void)out_size;
    const float* tenOne    = (const float*)d_in[0];
    const float* tenTwo    = (const float*)d_in[1];
    const float* prev_flow = (const float*)d_in[2];
    const float* prev_feat = (const float*)d_in[3];
    const float* w_upflow  = (const float*)d_in[4];
    const float* b_upflow  = (const float*)d_in[5];
    const float* w_upfeat  = (const float*)d_in[6];
    const float* b_upfeat  = (const float*)d_in[7];
    const float* w1 = (const float*)d_in[8];   const float* b1 = (const float*)d_in[9];
    const float* w2 = (const float*)d_in[10];  const float* b2 = (const float*)d_in[11];
    const float* w3 = (const float*)d_in[12];  const float* b3 = (const float*)d_in[13];
    const float* w4 = (const float*)d_in[14];  const float* b4 = (const float*)d_in[15];
    const float* w5 = (const float*)d_in[16];  const float* b5 = (const float*)d_in[17];
    const float* w6 = (const float*)d_in[18];  const float* b6 = (const float*)d_in[19];

    float* flow = (float*)d_out;
    float* feat = flow + (size_t)Bn * 2 * HW;

    uint32_t* apack;
    cudaGetSymbolAddress((void**)&apack, g_Apack);

    const int NPIX = Bn * HW;

    // 0. weight pre-packs
    pack_all_kernel<<<(APACK_TOTAL + 255) / 256, 256>>>(w1, w2, w3, w4, w5, apack);
    {
        float* upw;
        cudaGetSymbolAddress((void**)&upw, g_upw);
        pack_upw_kernel<<<(4 * 663 * 8 + 255) / 256, 256>>>(w_upflow, w_upfeat, upw);
    }
    // 1. flow upconv (per-pixel, Cin=2)
    upflow_kernel<<<(NPIX + 255) / 256, 256>>>(prev_flow, b_upflow, feat);
    // 2. upfeat upconv (tiled)
    upfeat_tiled_kernel<<<dim3(32, Bn), 256>>>(prev_feat, b_upfeat, feat);
    // 3. tenOne
    copy_t1_kernel<<<(NPIX + 255) / 256, 256>>>(tenOne, feat);
    // 4. warp tenTwo
    warp_kernel<<<(NPIX + 255) / 256, 256>>>(tenTwo, feat);
    // 5. correlation
    corr_kernel<<<dim3(W / 32, H / 4, Bn), 128>>>(tenOne, feat);

    // 6-10. fp16 mma conv tower (quad-interleaved)
    conv_mma6_kernel<181, 128, 128, 4><<<dim3(128, Bn), 128>>>(
        OFF_VOL / 16, (const uint4*)(apack + APACK_OFF1), b1,
        feat + (size_t)OFF_C1 * HW, OFF_C1);
    conv_mma6_kernel<309, 128, 128, 4><<<dim3(128, Bn), 128>>>(
        OFF_C1 / 16, (const uint4*)(apack + APACK_OFF2), b2,
        feat + (size_t)OFF_C2 * HW, OFF_C2);
    conv_mma6_kernel<437, 96, 96, 5><<<dim3(128, Bn), 96>>>(
        OFF_C2 / 16, (const uint4*)(apack + APACK_OFF3), b3,
        feat + (size_t)OFF_C3 * HW, OFF_C3);
    conv_mma6_kernel<533, 64, 64, 8><<<dim3(128, Bn), 64>>>(
        OFF_C3 / 16, (const uint4*)(apack + APACK_OFF4), b4,
        feat + (size_t)OFF_C4 * HW, OFF_C4);
    conv_mma6_kernel<597, 32, 32, 12><<<dim3(128, Bn), 32>>>(
        OFF_C4 / 16, (const uint4*)(apack + APACK_OFF5), b5,
        feat + (size_t)OFF_C5 * HW, OFF_C5);

    // 11. conv6 (Cout=2) -> flow, FFMA path
    conv3x3_kernel<2><<<dim3(1, 8, Bn), 256>>>(
        feat + (size_t)OFF_C5 * HW, w6, b6, flow,
        629, FEAT_STRIDE, 2 * HW);
}

// round 17
// speedup vs baseline: 1.1945x; 1.1945x over previous
#include <cuda_runtime.h>
#include <cuda_fp16.h>
#include <math.h>
#include <stdint.h>

// ---------------------------------------------------------------------------
#define Bn 8
#define H 64
#define W 128
#define HW (H * W)
#define C1CH 96
#define HIN 32
#define WIN 64
#define HWIN (HIN * WIN)
#define PREVC 661

#define FEAT_C 629
#define FEAT_STRIDE (FEAT_C * HW)

// [c5(32) | c4(64) | c3(96) | c2(128) | c1(128) | vol(81) | tenOne(96) | flow(2) | upfeat(2)]
#define OFF_C5   0
#define OFF_C4   32
#define OFF_C3   96
#define OFF_C2   192
#define OFF_C1   320
#define OFF_VOL  448
#define OFF_T1   529
#define OFF_FLOW 625
#define OFF_UPF  627

#define NQG 40                         // 640-channel padded space / 16

__device__ float g_warped[(size_t)Bn * C1CH * HW];

// quad-interleaved fp16 shadow: per (b, g16, pix): 4 u64 slots,
// slot s = {half2(ch 16g+2s, +1), half2(ch 16g+8+2s, +1)}.
__device__ unsigned long long g_halfq[(size_t)Bn * NQG * HW * 4];

// fp16 A-fragments, chunk = 144 k; k-order: tap-major (ks=tap), channel-minor
#define APACK_OFF1 0
#define APACK_OFF2 110592      // + 12*9*8*128
#define APACK_OFF3 294912      // + 20*9*8*128
#define APACK_OFF4 488448      // + 28*9*6*128
#define APACK_OFF5 645120      // + 34*9*4*128
#define APACK_TOTAL 732672     // + 38*9*2*128
__device__ uint32_t g_Apack[APACK_TOTAL];

// per-parity packed upconv weights: [parity 4][ci 663][8 floats]
__device__ float g_upw[4 * 663 * 8];

// upfeat channel-chunk partials: [chunk 4][b][cout 2][HW]
__device__ float g_upscr[4 * Bn * 2 * HW];

// ---------------------------------------------------------------------------
__device__ __forceinline__ uint32_t smem_u32(const void* p) {
    uint32_t a;
    asm("{ .reg .u64 t; cvta.to.shared.u64 t, %1; cvt.u32.u64 %0, t; }" : "=r"(a) : "l"(p));
    return a;
}
__device__ __forceinline__ void cp_async16(uint32_t dst, const void* src) {
    asm volatile("cp.async.ca.shared.global [%0], [%1], 16;" :: "r"(dst), "l"(src));
}
__device__ __forceinline__ void cp_async4(uint32_t dst, const void* src) {
    asm volatile("cp.async.ca.shared.global [%0], [%1], 4;" :: "r"(dst), "l"(src));
}
#define CP_COMMIT() asm volatile("cp.async.commit_group;")
#define CP_WAIT0()  asm volatile("cp.async.wait_group 0;")
#define CP_WAIT1()  asm volatile("cp.async.wait_group 1;")
#define CP_WAIT2()  asm volatile("cp.async.wait_group 2;")

// scalar write into the quad-interleaved shadow
__device__ __forceinline__ void st_half(int b, int ch, int pix, float v) {
    int g16 = ch >> 4, r = ch & 15;
    int pos = 4 * ((r & 7) >> 1) + ((r >> 3) << 1) + (r & 1);
    __half* hp = (__half*)g_halfq + (((size_t)b * NQG + g16) * HW + pix) * 16 + pos;
    *hp = __float2half_rn(v);
}

__device__ __forceinline__ uint32_t pk2h(float a, float b) {
    __half ha = __float2half_rn(a), hb = __float2half_rn(b);
    return (uint32_t)__half_as_ushort(ha) | ((uint32_t)__half_as_ushort(hb) << 16);
}

#define MMA_F16(c, a0, a1, a2, a3, b0v, b1v) \
    asm volatile( \
        "mma.sync.aligned.m16n8k16.row.col.f32.f16.f16.f32 " \
        "{%0,%1,%2,%3}, {%4,%5,%6,%7}, {%8,%9}, {%0,%1,%2,%3};" \
        : "+f"((c)[0]), "+f"((c)[1]), "+f"((c)[2]), "+f"((c)[3]) \
        : "r"(a0), "r"(a1), "r"(a2), "r"(a3), \
          "r"(b0v), "r"(b1v))

// ---------------------------------------------------------------------------
// Weight pre-pack (unchanged layout)
// ---------------------------------------------------------------------------
__device__ __forceinline__ void pack_one(const float* w, uint32_t* dst, int idx,
                                         int Cin, int Cout)
{
    int MFT = Cout >> 4;
    int reg = idx & 3, lane = (idx >> 2) & 31;
    int u = idx >> 7;
    int mf = u % MFT;
    int v3 = u / MFT;
    int ks = v3 % 9, kt = v3 / 9;
    int m = mf * 16 + (lane >> 2) + 8 * (reg & 1);
    int ch = kt * 16 + (lane & 3) * 2 + 8 * (reg >> 1);
    float v0 = (ch     < Cin) ? w[((size_t)m * Cin + ch)     * 9 + ks] : 0.f;
    float v1 = (ch + 1 < Cin) ? w[((size_t)m * Cin + ch + 1) * 9 + ks] : 0.f;
    __half h0 = __float2half_rn(v0), h1 = __float2half_rn(v1);
    dst[idx] = (uint32_t)__half_as_ushort(h0) | ((uint32_t)__half_as_ushort(h1) << 16);
}

__global__ void pack_all_kernel(const float* __restrict__ w1, const float* __restrict__ w2,
                                const float* __restrict__ w3, const float* __restrict__ w4,
                                const float* __restrict__ w5, uint32_t* __restrict__ dst)
{
    int idx = blockIdx.x * blockDim.x + threadIdx.x;
    if (idx >= APACK_TOTAL) return;
    if      (idx < APACK_OFF2) pack_one(w1, dst + APACK_OFF1, idx - APACK_OFF1, 181, 128);
    else if (idx < APACK_OFF3) pack_one(w2, dst + APACK_OFF2, idx - APACK_OFF2, 309, 128);
    else if (idx < APACK_OFF4) pack_one(w3, dst + APACK_OFF3, idx - APACK_OFF3, 437, 96);
    else if (idx < APACK_OFF5) pack_one(w4, dst + APACK_OFF4, idx - APACK_OFF4, 533, 64);
    else                       pack_one(w5, dst + APACK_OFF5, idx - APACK_OFF5, 597, 32);
}

// per-parity upconv weight pack: [parity][ci_all(663)][8]
__global__ void pack_upw_kernel(const float* __restrict__ wF, const float* __restrict__ wU,
                                float* __restrict__ dst)
{
    int idx = blockIdx.x * blockDim.x + threadIdx.x;
    if (idx >= 4 * 663 * 8) return;
    int j = idx & 7;
    int q = idx >> 3;
    int ci_all = q % 663, parity = q / 663;
    int py = parity >> 1, px = parity & 1;
    int ky0 = 1 + py, ky1 = py ? 0 : 3;
    int kx0 = 1 + px, kx1 = px ? 0 : 3;
    int cout = j >> 2, tp = j & 3;
    int ky = (tp < 2) ? ky0 : ky1;
    int kx = (tp & 1) ? kx1 : kx0;
    const float* src;
    int ci;
    if (ci_all < 2) { src = wF; ci = ci_all; }
    else            { src = wU; ci = ci_all - 2; }
    dst[idx] = src[(size_t)ci * 32 + cout * 16 + ky * 4 + kx];
}

// ---------------------------------------------------------------------------
// Flow upconv: per-pixel, Cin = 2 (trivial)
// ---------------------------------------------------------------------------
__global__ void upflow_kernel(const float* __restrict__ inF, const float* __restrict__ bF,
                              float* __restrict__ feat)
{
    int gid = blockIdx.x * blockDim.x + threadIdx.x;
    if (gid >= Bn * HW) return;
    int b = gid / HW, pix = gid - b * HW;
    int y = pix / W, x = pix - (pix / W) * W;
    int iy0 = y >> 1, iy1 = (y >> 1) + ((y & 1) ? 1 : -1);
    int ix0 = x >> 1, ix1 = (x >> 1) + ((x & 1) ? 1 : -1);
    bool vy1 = (unsigned)iy1 < HIN, vx1 = (unsigned)ix1 < WIN;
    int parity = (y & 1) * 2 + (x & 1);
    const float* wb = g_upw + (size_t)parity * (663 * 8);
    float a0 = bF[0], a1 = bF[1];
    const float* pin = inF + (size_t)b * 2 * HWIN;
    int p00 = iy0 * WIN + ix0, p01 = iy0 * WIN + ix1;
    int p10 = iy1 * WIN + ix0, p11 = iy1 * WIN + ix1;
#pragma unroll
    for (int ci = 0; ci < 2; ci++) {
        const float* p = pin + (size_t)ci * HWIN;
        float4 f0 = *(const float4*)(wb + ci * 8);
        float4 f1 = *(const float4*)(wb + ci * 8 + 4);
        float u0 = p[p00];
        float u1 = vx1 ? p[p01] : 0.f;
        float u2 = vy1 ? p[p10] : 0.f;
        float u3 = (vy1 && vx1) ? p[p11] : 0.f;
        a0 += u0 * f0.x + u1 * f0.y + u2 * f0.z + u3 * f0.w;
        a1 += u0 * f1.x + u1 * f1.y + u2 * f1.z + u3 * f1.w;
    }
    size_t o = (size_t)b * FEAT_STRIDE + (size_t)OFF_FLOW * HW + pix;
    feat[o]      = a0;
    feat[o + HW] = a1;
    st_half(b, OFF_FLOW,     pix, a0);
    st_half(b, OFF_FLOW + 1, pix, a1);
}

// ---------------------------------------------------------------------------
// upfeat upconv, stage 1: channel-chunk partials.
// grid (32 tiles, Bn, 4 chunks), 256 threads. 64x4 output tile per CTA.
// Depth-3 cp.async ring over channels; partial sums -> g_upscr.
// ---------------------------------------------------------------------------
__global__ __launch_bounds__(256) void upfeat_part_kernel(const float* __restrict__ in)
{
    __shared__ float s_in[4][136];
    __shared__ float s_w[4][32];
    const int tid = threadIdx.x;
    const int x0 = (blockIdx.x & 1) << 6;
    const int y0 = (blockIdx.x >> 1) << 2;
    const int b = blockIdx.y;
    const int chunk = blockIdx.z;
    const int c0 = chunk * 166;
    const int cEnd = (c0 + 166 < PREVC) ? c0 + 166 : PREVC;
    const int x = x0 + (tid & 63), y = y0 + (tid >> 6);
    const int Y = y0 >> 1, X = x0 >> 1;
    const float* pin = in + (size_t)b * PREVC * HWIN;
    const uint32_t aIn = smem_u32(s_in);
    const uint32_t aW  = smem_u32(s_w);

    const int ry0 = 1 + ((y - y0) >> 1);
    const int ry1 = (y & 1) ? ry0 + 1 : ry0 - 1;
    const int rx0 = 1 + ((x - x0) >> 1);
    const int rx1 = (x & 1) ? rx0 + 1 : rx0 - 1;
    const int parity = (y & 1) * 2 + (x & 1);

    auto stageCh = [&](int ci, int s) {
        if (ci >= cEnd) return;
        if (tid < 136) {
            int r = tid / 34, c = tid - (tid / 34) * 34;
            int iy = Y - 1 + r, ix = X - 1 + c;
            if ((unsigned)iy < HIN && (unsigned)ix < WIN)
                cp_async4(aIn + (uint32_t)((s * 136 + tid) * 4),
                          pin + (size_t)ci * HWIN + iy * WIN + ix);
            else
                s_in[s][tid] = 0.f;
        } else if (tid < 168) {
            int j = tid - 136;
            cp_async4(aW + (uint32_t)((s * 32 + j) * 4),
                      g_upw + (size_t)(j >> 3) * (663 * 8) + (size_t)(ci + 2) * 8 + (j & 7));
        }
    };

    stageCh(c0, 0);     CP_COMMIT();
    stageCh(c0 + 1, 1); CP_COMMIT();
    stageCh(c0 + 2, 2); CP_COMMIT();

    float a0 = 0.f, a1 = 0.f;
    for (int ci = c0; ci < cEnd; ci++) {
        const int s = (ci - c0) & 3;
        CP_WAIT2();
        __syncthreads();
        stageCh(ci + 3, (ci - c0 + 3) & 3);
        CP_COMMIT();
        const float* si = s_in[s];
        const float* sw = s_w[s] + parity * 8;
        float u0 = si[ry0 * 34 + rx0];
        float u1 = si[ry0 * 34 + rx1];
        float u2 = si[ry1 * 34 + rx0];
        float u3 = si[ry1 * 34 + rx1];
        float4 f0 = *(const float4*)(sw);
        float4 f1 = *(const float4*)(sw + 4);
        a0 += u0 * f0.x + u1 * f0.y + u2 * f0.z + u3 * f0.w;
        a1 += u0 * f1.x + u1 * f1.y + u2 * f1.z + u3 * f1.w;
    }
    int pix = y * W + x;
    float* scr = g_upscr + ((size_t)(chunk * Bn + b) * 2) * HW;
    scr[pix]      = a0;
    scr[HW + pix] = a1;
}

// stage 2: reduce 4 partials + bias -> feat + shadow
__global__ void upfeat_reduce_kernel(const float* __restrict__ bU, float* __restrict__ feat)
{
    int gid = blockIdx.x * blockDim.x + threadIdx.x;
    if (gid >= Bn * HW) return;
    int b = gid / HW, pix = gid - b * HW;
    float a0 = bU[0], a1 = bU[1];
#pragma unroll
    for (int c = 0; c < 4; c++) {
        const float* scr = g_upscr + ((size_t)(c * Bn + b) * 2) * HW;
        a0 += scr[pix];
        a1 += scr[HW + pix];
    }
    size_t o = (size_t)b * FEAT_STRIDE + (size_t)OFF_UPF * HW + pix;
    feat[o]      = a0;
    feat[o + HW] = a1;
    st_half(b, OFF_UPF,     pix, a0);
    st_half(b, OFF_UPF + 1, pix, a1);
}

// ---------------------------------------------------------------------------
// tenOne -> feat + shadow; full 16-ch groups written as 2x ST.128 per pixel
// ---------------------------------------------------------------------------
__global__ void copy_t1_kernel(const float* __restrict__ t1, float* __restrict__ feat)
{
    int gid = blockIdx.x * blockDim.x + threadIdx.x;
    if (gid >= Bn * HW) return;
    int b = gid / HW, pix = gid - b * HW;
    const float* src = t1 + (size_t)b * C1CH * HW + pix;
    float* dstF = feat + (size_t)b * FEAT_STRIDE + (size_t)OFF_T1 * HW + pix;
    __half* hbase = (__half*)g_halfq + ((size_t)b * NQG) * HW * 16;

#pragma unroll
    for (int j = 0; j < 15; j++) {
        float v = src[(size_t)j * HW];
        dstF[(size_t)j * HW] = v;
        st_half(b, 529 + j, pix, v);
    }
#pragma unroll
    for (int gi = 0; gi < 5; gi++) {
        int j0 = 15 + gi * 16;
        float w[16];
#pragma unroll
        for (int s = 0; s < 16; s++) {
            w[s] = src[(size_t)(j0 + s) * HW];
            dstF[(size_t)(j0 + s) * HW] = w[s];
        }
        uint4* dst = (uint4*)(hbase + ((size_t)(34 + gi) * HW + pix) * 16);
        dst[0] = make_uint4(pk2h(w[0], w[1]), pk2h(w[8],  w[9]),
                            pk2h(w[2], w[3]), pk2h(w[10], w[11]));
        dst[1] = make_uint4(pk2h(w[4], w[5]), pk2h(w[12], w[13]),
                            pk2h(w[6], w[7]), pk2h(w[14], w[15]));
    }
    {
        float v = src[(size_t)95 * HW];
        dstF[(size_t)95 * HW] = v;
        st_half(b, 624, pix, v);
    }
}

__global__ void warp_kernel(const float* __restrict__ tenTwo, const float* __restrict__ feat)
{
    int gid = blockIdx.x * blockDim.x + threadIdx.x;
    if (gid >= Bn * HW) return;
    int b = gid / HW;
    int pix = gid - b * HW;
    int y = pix / W, x = pix - (pix / W) * W;

    const float* fl = feat + (size_t)b * FEAT_STRIDE + (size_t)OFF_FLOW * HW + pix;
    float px = (float)x + fl[0]  * 1.25f;
    float py = (float)y + fl[HW] * 1.25f;
    float fx = floorf(px), fy = floorf(py);
    float wx = px - fx, wy = py - fy;
    int ix0 = (int)fx, iy0 = (int)fy;
    int ix1 = ix0 + 1, iy1 = iy0 + 1;
    bool vx0 = (unsigned)ix0 < W, vx1 = (unsigned)ix1 < W;
    bool vy0 = (unsigned)iy0 < H, vy1 = (unsigned)iy1 < H;
    float w00 = (1.f - wy) * (1.f - wx), w01 = (1.f - wy) * wx;
    float w10 = wy * (1.f - wx),         w11 = wy * wx;
    int o00 = iy0 * W + ix0, o01 = iy0 * W + ix1;
    int o10 = iy1 * W + ix0, o11 = iy1 * W + ix1;

    const float* t = tenTwo + (size_t)b * C1CH * HW;
    float* o = g_warped + (size_t)b * C1CH * HW + pix;
    for (int c = 0; c < C1CH; c++) {
        const float* tc = t + (size_t)c * HW;
        float v = 0.f;
        if (vy0 && vx0) v += tc[o00] * w00;
        if (vy0 && vx1) v += tc[o01] * w01;
        if (vy1 && vx0) v += tc[o10] * w10;
        if (vy1 && vx1) v += tc[o11] * w11;
        o[(size_t)c * HW] = v;
    }
}

__global__ __launch_bounds__(128) void corr_kernel(const float* __restrict__ tenOne,
                                                   float* __restrict__ feat)
{
    __shared__ float s_f1[4][32];
    __shared__ float s_w2[12][40];
    int tid = threadIdx.x;
    int tx = tid & 31, ty = tid >> 5;
    int x0 = blockIdx.x * 32, y0 = blockIdx.y * 4, b = blockIdx.z;

    float acc[81];
#pragma unroll
    for (int d = 0; d < 81; d++) acc[d] = 0.f;

    const float* f1 = tenOne + (size_t)b * C1CH * HW;
    const float* f2 = g_warped + (size_t)b * C1CH * HW;

    for (int c = 0; c < C1CH; c++) {
        const float* f1c = f1 + (size_t)c * HW;
        const float* f2c = f2 + (size_t)c * HW;
        __syncthreads();
        s_f1[ty][tx] = f1c[(y0 + ty) * W + x0 + tx];
#pragma unroll
        for (int i = 0; i < 4; i++) {
            int idx = tid + i * 128;
            if (idx < 480) {
                int r = idx / 40, cc = idx - (idx / 40) * 40;
                int gy = y0 - 4 + r, gx = x0 - 4 + cc;
                float v = 0.f;
                if ((unsigned)gy < H && (unsigned)gx < W) v = f2c[gy * W + gx];
                s_w2[r][cc] = v;
            }
        }
        __syncthreads();
        float a = s_f1[ty][tx];
#pragma unroll
        for (int dy = 0; dy < 9; dy++)
#pragma unroll
            for (int dx = 0; dx < 9; dx++)
                acc[dy * 9 + dx] += a * s_w2[ty + dy][tx + dx];
    }

    int pix = (y0 + ty) * W + x0 + tx;
    size_t obase = (size_t)b * FEAT_STRIDE + (size_t)OFF_VOL * HW + pix;
    const float inv = 1.f / 96.f;
    float r[81];
#pragma unroll
    for (int d = 0; d < 81; d++) {
        float v = acc[d] * inv;
        v = (v >= 0.f) ? v : 0.1f * v;
        r[d] = v;
        feat[obase + (size_t)d * HW] = v;
    }
    __half* hbase = (__half*)g_halfq + ((size_t)b * NQG) * HW * 16;
#pragma unroll
    for (int gi = 0; gi < 5; gi++) {
        int d0 = gi * 16;
        uint4* dst = (uint4*)(hbase + ((size_t)(28 + gi) * HW + pix) * 16);
        dst[0] = make_uint4(pk2h(r[d0 + 0], r[d0 + 1]), pk2h(r[d0 + 8],  r[d0 + 9]),
                            pk2h(r[d0 + 2], r[d0 + 3]), pk2h(r[d0 + 10], r[d0 + 11]));
        dst[1] = make_uint4(pk2h(r[d0 + 4], r[d0 + 5]), pk2h(r[d0 + 12], r[d0 + 13]),
                            pk2h(r[d0 + 6], r[d0 + 7]), pk2h(r[d0 + 14], r[d0 + 15]));
    }
    st_half(b, 528, pix, r[80]);
}

// ---------------------------------------------------------------------------
// FFMA direct 3x3 conv (conv6, Cout=2)
// ---------------------------------------------------------------------------
template <int COUT_BLK>
__global__ __launch_bounds__(256) void conv3x3_kernel(
    const float* __restrict__ in, const float* __restrict__ w,
    const float* __restrict__ bias, float* __restrict__ out,
    int Cin, int inStride, int outStride)
{
    __shared__ float s_in[18][66];
    __shared__ float s_w[COUT_BLK * 9];
    const int tid = threadIdx.x;
    const int tx = tid & 15, ty = tid >> 4;
    const int g = blockIdx.x;
    const int tileX = blockIdx.y & 1, tileY = blockIdx.y >> 1;
    const int b = blockIdx.z;
    const int x0 = tileX * 64, y0 = tileY * 16;

    const float* inB = in + (size_t)b * inStride;
    float acc[COUT_BLK][4];
#pragma unroll
    for (int c = 0; c < COUT_BLK; c++)
#pragma unroll
        for (int p = 0; p < 4; p++) acc[c][p] = 0.f;

    for (int ci = 0; ci < Cin; ci++) {
        const float* ch = inB + (size_t)ci * HW;
#pragma unroll
        for (int i = 0; i < 5; i++) {
            int idx = tid + i * 256;
            if (idx < 18 * 66) {
                int r = idx / 66, c = idx - (idx / 66) * 66;
                int gy = y0 - 1 + r, gx = x0 - 1 + c;
                float v = 0.f;
                if ((unsigned)gy < H && (unsigned)gx < W) v = ch[gy * W + gx];
                s_in[r][c] = v;
            }
        }
        if (tid < COUT_BLK * 9)
            s_w[tid] = w[((size_t)(g * COUT_BLK + tid / 9) * Cin + ci) * 9 + tid % 9];
        __syncthreads();

        float r0[6], r1[6], r2[6];
#pragma unroll
        for (int k = 0; k < 6; k++) {
            r0[k] = s_in[ty][tx * 4 + k];
            r1[k] = s_in[ty + 1][tx * 4 + k];
            r2[k] = s_in[ty + 2][tx * 4 + k];
        }
#pragma unroll
        for (int co = 0; co < COUT_BLK; co++) {
            float w0 = s_w[co * 9 + 0], w1v = s_w[co * 9 + 1], w2v = s_w[co * 9 + 2];
            float w3v = s_w[co * 9 + 3], w4v = s_w[co * 9 + 4], w5v = s_w[co * 9 + 5];
            float w6v = s_w[co * 9 + 6], w7v = s_w[co * 9 + 7], w8v = s_w[co * 9 + 8];
#pragma unroll
            for (int p = 0; p < 4; p++) {
                float s = acc[co][p];
                s += w0  * r0[p]; s += w1v * r0[p + 1]; s += w2v * r0[p + 2];
                s += w3v * r1[p]; s += w4v * r1[p + 1]; s += w5v * r1[p + 2];
                s += w6v * r2[p]; s += w7v * r2[p + 1]; s += w8v * r2[p + 2];
                acc[co][p] = s;
            }
        }
        __syncthreads();
    }

#pragma unroll
    for (int co = 0; co < COUT_BLK; co++) {
        float bi = bias[g * COUT_BLK + co];
        float* o = out + (size_t)b * outStride + (size_t)(g * COUT_BLK + co) * HW
                 + (y0 + ty) * W + x0 + tx * 4;
#pragma unroll
        for (int p = 0; p < 4; p++) {
            float v = acc[co][p] + bi;
            o[p] = (v >= 0.f) ? v : 0.1f * v;
        }
    }
}

// ---------------------------------------------------------------------------
// conv_mma6: N=64 tiles, quad-interleaved B -> one LDS.64 per b-fragment.
// ---------------------------------------------------------------------------
#define SRQ 268                 // u64 per staged row
#define BUFQ (3 * SRQ)          // u64 per buffer

template <int Cin, int Cout, int THREADS, int MINB>
__global__ __launch_bounds__(THREADS, MINB) void conv_mma6_kernel(
    int base16,
    const uint4* __restrict__ Apack,
    const float* __restrict__ bias,
    float* __restrict__ outBase,
    int outOff)
{
    constexpr int nC  = (Cin + 15) / 16;
    constexpr int MFT = Cout / 16;

    __shared__ unsigned long long rawq[2 * BUFQ];
    const int tid = threadIdx.x, lane = tid & 31, wrp = tid >> 5;
    const int wm0 = wrp * 32;
    const int y  = blockIdx.x >> 1;
    const int x0 = (blockIdx.x & 1) << 6;
    const int b  = blockIdx.y;
    const unsigned long long* inQ = g_halfq + (size_t)b * NQG * HW * 4;
    const uint32_t rawAddr = smem_u32(rawq);
    const uint4* apw = Apack + (size_t)(wrp * 2) * 32 + lane;

    float acc[2][8][4];
#pragma unroll
    for (int mi = 0; mi < 2; mi++)
#pragma unroll
        for (int nf = 0; nf < 8; nf++)
#pragma unroll
            for (int p = 0; p < 4; p++) acc[mi][nf][p] = 0.f;

    auto stage = [&](int kt, int bufsel) {
        const unsigned long long* src = inQ + (size_t)(base16 + kt) * HW * 4;
        for (int i = tid; i < 384; i += THREADS) {
            int r = i >> 7, j = i & 127;
            int p = j >> 1, hs = j & 1;
            int yr = y + r - 1;
            uint32_t didx = (uint32_t)(bufsel * BUFQ + r * SRQ + (1 + p) * 4 + hs * 2);
            if ((unsigned)yr < (unsigned)H)
                cp_async16(rawAddr + didx * 8, src + ((size_t)yr * W + x0 + p) * 4 + hs * 2);
            else
                *(uint4*)(rawq + didx) = make_uint4(0u, 0u, 0u, 0u);
        }
        for (int e = tid; e < 12; e += THREADS) {
            int r = e >> 2, j = e & 3;
            int side = j >> 1, hs = j & 1;
            int yr = y + r - 1;
            int x = side ? (x0 + 64) : (x0 - 1);
            uint32_t didx = (uint32_t)(bufsel * BUFQ + r * SRQ + (side ? 260 : 0) + hs * 2);
            if ((unsigned)yr < (unsigned)H && (unsigned)x < (unsigned)W)
                cp_async16(rawAddr + didx * 8, src + ((size_t)yr * W + x) * 4 + hs * 2);
            else
                *(uint4*)(rawq + didx) = make_uint4(0u, 0u, 0u, 0u);
        }
    };

    stage(0, 0);
    CP_COMMIT();

    const int t = lane & 3;
    const int g = lane >> 2;

    uint4 ah0, ah1;
    { const uint4* p = apw; ah0 = p[0]; ah1 = p[32]; }

    for (int kt = 0; kt < nC; kt++) {
        const int buf = kt & 1;
        if (kt + 1 < nC) {
            stage(kt + 1, buf ^ 1);
            CP_COMMIT();
            CP_WAIT1();
        } else {
            CP_WAIT0();
        }
        __syncthreads();

        const unsigned long long* rbq = rawq + buf * BUFQ;

#pragma unroll
        for (int ks = 0; ks < 9; ks++) {
            uint4 nh0, nh1;
            {
                int nkt = kt, nks = ks + 1;
                if (nks == 9) { nkt = kt + 1; nks = 0; }
                if (nkt < nC) {
                    const uint4* p = apw + (size_t)((nkt * 9 + nks) * MFT) * 32;
                    nh0 = p[0]; nh1 = p[32];
                } else {
                    nh0 = nh1 = make_uint4(0u, 0u, 0u, 0u);
                }
            }

            const int dy = ks / 3, dx = ks % 3;
            const unsigned long long* bp = rbq + dy * SRQ + (g + dx) * 4 + t;

#pragma unroll
            for (int nf = 0; nf < 8; nf += 2) {
                unsigned long long vA = bp[nf * 32];
                unsigned long long vB = bp[nf * 32 + 32];
                uint32_t bA0 = (uint32_t)vA, bA1 = (uint32_t)(vA >> 32);
                uint32_t bB0 = (uint32_t)vB, bB1 = (uint32_t)(vB >> 32);
                MMA_F16(acc[0][nf],     ah0.x, ah0.y, ah0.z, ah0.w, bA0, bA1);
                MMA_F16(acc[1][nf],     ah1.x, ah1.y, ah1.z, ah1.w, bA0, bA1);
                MMA_F16(acc[0][nf + 1], ah0.x, ah0.y, ah0.z, ah0.w, bB0, bB1);
                MMA_F16(acc[1][nf + 1], ah1.x, ah1.y, ah1.z, ah1.w, bB0, bB1);
            }
            ah0 = nh0; ah1 = nh1;
        }
        __syncthreads();
    }

    const int q = lane & 3, g2 = lane >> 2;
    float* outB = outBase + (size_t)b * FEAT_STRIDE;
    __half* hq = (__half*)g_halfq + ((size_t)b * NQG) * HW * 16;
#pragma unroll
    for (int mi = 0; mi < 2; mi++) {
        int m0 = wm0 + mi * 16 + g2;
        int am = outOff + m0;
        float bLo = __ldg(bias + m0), bHi = __ldg(bias + m0 + 8);
        float* o0 = outB + (size_t)m0 * HW;
        float* o1 = o0 + 8 * HW;
        size_t hb = (size_t)(am >> 4) * HW * 16 + 4 * ((am & 15) >> 1) + (am & 1);
#pragma unroll
        for (int nf = 0; nf < 8; nf++) {
            int off = y * W + x0 + nf * 8 + 2 * q;
            float v0 = acc[mi][nf][0] + bLo, v1 = acc[mi][nf][1] + bLo;
            float v2 = acc[mi][nf][2] + bHi, v3 = acc[mi][nf][3] + bHi;
            v0 = (v0 >= 0.f) ? v0 : 0.1f * v0;
            v1 = (v1 >= 0.f) ? v1 : 0.1f * v1;
            v2 = (v2 >= 0.f) ? v2 : 0.1f * v2;
            v3 = (v3 >= 0.f) ? v3 : 0.1f * v3;
            *(float2*)(o0 + off) = make_float2(v0, v1);
            *(float2*)(o1 + off) = make_float2(v2, v3);
            size_t h = hb + (size_t)off * 16;
            hq[h]      = __float2half_rn(v0);
            hq[h + 2]  = __float2half_rn(v2);
            hq[h + 16] = __float2half_rn(v1);
            hq[h + 18] = __float2half_rn(v3);
        }
    }
}

// ---------------------------------------------------------------------------
// Launch
// ---------------------------------------------------------------------------
extern "C" void kernel_launch(void* const* d_in, const int* in_sizes, int n_in,
                              void* d_out, int out_size)
{
    (void)in_sizes; (void)n_in; (void)out_size;
    const float* tenOne    = (const float*)d_in[0];
    const float* tenTwo    = (const float*)d_in[1];
    const float* prev_flow = (const float*)d_in[2];
    const float* prev_feat = (const float*)d_in[3];
    const float* w_upflow  = (const float*)d_in[4];
    const float* b_upflow  = (const float*)d_in[5];
    const float* w_upfeat  = (const float*)d_in[6];
    const float* b_upfeat  = (const float*)d_in[7];
    const float* w1 = (const float*)d_in[8];   const float* b1 = (const float*)d_in[9];
    const float* w2 = (const float*)d_in[10];  const float* b2 = (const float*)d_in[11];
    const float* w3 = (const float*)d_in[12];  const float* b3 = (const float*)d_in[13];
    const float* w4 = (const float*)d_in[14];  const float* b4 = (const float*)d_in[15];
    const float* w5 = (const float*)d_in[16];  const float* b5 = (const float*)d_in[17];
    const float* w6 = (const float*)d_in[18];  const float* b6 = (const float*)d_in[19];

    float* flow = (float*)d_out;
    float* feat = flow + (size_t)Bn * 2 * HW;

    uint32_t* apack;
    cudaGetSymbolAddress((void**)&apack, g_Apack);

    const int NPIX = Bn * HW;

    // 0. weight pre-packs
    pack_all_kernel<<<(APACK_TOTAL + 255) / 256, 256>>>(w1, w2, w3, w4, w5, apack);
    {
        float* upw;
        cudaGetSymbolAddress((void**)&upw, g_upw);
        pack_upw_kernel<<<(4 * 663 * 8 + 255) / 256, 256>>>(w_upflow, w_upfeat, upw);
    }
    // 1. flow upconv (per-pixel, Cin=2)
    upflow_kernel<<<(NPIX + 255) / 256, 256>>>(prev_flow, b_upflow, feat);
    // 2. upfeat upconv: channel-chunk partials + reduce
    upfeat_part_kernel<<<dim3(32, Bn, 4), 256>>>(prev_feat);
    upfeat_reduce_kernel<<<(NPIX + 255) / 256, 256>>>(b_upfeat, feat);
    // 3. tenOne
    copy_t1_kernel<<<(NPIX + 255) / 256, 256>>>(tenOne, feat);
    // 4. warp tenTwo
    warp_kernel<<<(NPIX + 255) / 256, 256>>>(tenTwo, feat);
    // 5. correlation
    corr_kernel<<<dim3(W / 32, H / 4, Bn), 128>>>(tenOne, feat);

    // 6-10. fp16 mma conv tower (quad-interleaved)
    conv_mma6_kernel<181, 128, 128, 4><<<dim3(128, Bn), 128>>>(
        OFF_VOL / 16, (const uint4*)(apack + APACK_OFF1), b1,
        feat + (size_t)OFF_C1 * HW, OFF_C1);
    conv_mma6_kernel<309, 128, 128, 4><<<dim3(128, Bn), 128>>>(
        OFF_C1 / 16, (const uint4*)(apack + APACK_OFF2), b2,
        feat + (size_t)OFF_C2 * HW, OFF_C2);
    conv_mma6_kernel<437, 96, 96, 5><<<dim3(128, Bn), 96>>>(
        OFF_C2 / 16, (const uint4*)(apack + APACK_OFF3), b3,
        feat + (size_t)OFF_C3 * HW, OFF_C3);
    conv_mma6_kernel<533, 64, 64, 8><<<dim3(128, Bn), 64>>>(
        OFF_C3 / 16, (const uint4*)(apack + APACK_OFF4), b4,
        feat + (size_t)OFF_C4 * HW, OFF_C4);
    conv_mma6_kernel<597, 32, 32, 12><<<dim3(128, Bn), 32>>>(
        OFF_C4 / 16, (const uint4*)(apack + APACK_OFF5), b5,
        feat + (size_t)OFF_C5 * HW, OFF_C5);

    // 11. conv6 (Cout=2) -> flow, FFMA path
    conv3x3_kernel<2><<<dim3(1, 8, Bn), 256>>>(
        feat + (size_t)OFF_C5 * HW, w6, b6, flow,
        629, FEAT_STRIDE, 2 * HW);
}